// round 1
// baseline (speedup 1.0000x reference)
#include <cuda_runtime.h>

#define Ls 1024
#define Bb 4
#define Es 1024
#define Hs 16
#define HDs 64
#define LB (Ls*Bb)        // 4096
#define BH (Bb*Hs)        // 64
#define LL (Ls*Ls)        // 1048576

// Scratch (device globals — allocation-free)
__device__ float g_q[LB*Es];
__device__ float g_k[LB*Es];
__device__ float g_v[LB*Es];
__device__ float g_ctx[LB*Es];
__device__ float g_s[BH*LL];      // 256 MB scores/weights

// ---------------------------------------------------------------------------
// Generic NT SGEMM: C[4096,1024] = A[4096,1024] @ W[1024,1024]^T + bias
// 64x64 tile, BK=16, 256 threads, 4x4 register micro-tile.
// ---------------------------------------------------------------------------
__global__ __launch_bounds__(256) void sgemm_nt_kernel(
    const float* __restrict__ A, const float* __restrict__ W,
    const float* __restrict__ bias, float* __restrict__ C)
{
    const int K = 1024, N = 1024;
    __shared__ float As[16][65];
    __shared__ float Bs[16][65];
    const int tx = threadIdx.x, ty = threadIdx.y;
    const int tid = ty * 16 + tx;
    const int row0 = blockIdx.y * 64;
    const int col0 = blockIdx.x * 64;

    float acc[4][4] = {};

    for (int k0 = 0; k0 < K; k0 += 16) {
        #pragma unroll
        for (int t = 0; t < 4; t++) {              // 64*16/256 = 4
            int idx = tid + t * 256;
            int m = idx >> 4, k = idx & 15;
            As[k][m] = A[(row0 + m) * K + k0 + k];
        }
        #pragma unroll
        for (int t = 0; t < 4; t++) {
            int idx = tid + t * 256;
            int n = idx >> 4, k = idx & 15;
            Bs[k][n] = W[(col0 + n) * K + k0 + k];
        }
        __syncthreads();
        #pragma unroll
        for (int k = 0; k < 16; k++) {
            float a[4], b[4];
            #pragma unroll
            for (int i = 0; i < 4; i++) a[i] = As[k][ty * 4 + i];
            #pragma unroll
            for (int j = 0; j < 4; j++) b[j] = Bs[k][tx * 4 + j];
            #pragma unroll
            for (int i = 0; i < 4; i++)
                #pragma unroll
                for (int j = 0; j < 4; j++)
                    acc[i][j] += a[i] * b[j];
        }
        __syncthreads();
    }

    #pragma unroll
    for (int i = 0; i < 4; i++) {
        int r = row0 + ty * 4 + i;
        #pragma unroll
        for (int j = 0; j < 4; j++) {
            int c = col0 + tx * 4 + j;
            C[r * N + c] = acc[i][j] + bias[c];
        }
    }
}

// ---------------------------------------------------------------------------
// Scores: S[bh, i, j] = (1/8) * sum_d Q[bh,i,d]*K[bh,j,d] + mask[b,i,j]
// Q/K live interleaved in g_q/g_k as [L,B,E] with e = h*64+d.
// 64x64 tile, full K=64 in one shot.
// ---------------------------------------------------------------------------
__global__ __launch_bounds__(256) void scores_kernel(const float* __restrict__ mask)
{
    const int bh = blockIdx.z;
    const int b = bh >> 4;          // /H
    const int h = bh & 15;
    __shared__ float Qs[64][65];
    __shared__ float Ks[64][65];
    const int tx = threadIdx.x, ty = threadIdx.y;
    const int tid = ty * 16 + tx;
    const int i0 = blockIdx.y * 64;
    const int j0 = blockIdx.x * 64;

    #pragma unroll
    for (int t = 0; t < 16; t++) {              // 4096/256 = 16
        int idx = tid + t * 256;
        int r = idx >> 6, d = idx & 63;
        Qs[r][d] = g_q[((i0 + r) * Bb + b) * Es + h * 64 + d];
        Ks[r][d] = g_k[((j0 + r) * Bb + b) * Es + h * 64 + d];
    }
    __syncthreads();

    float acc[4][4] = {};
    #pragma unroll 8
    for (int k = 0; k < 64; k++) {
        float a[4], bb[4];
        #pragma unroll
        for (int i = 0; i < 4; i++) a[i] = Qs[ty * 4 + i][k];
        #pragma unroll
        for (int j = 0; j < 4; j++) bb[j] = Ks[tx * 4 + j][k];
        #pragma unroll
        for (int i = 0; i < 4; i++)
            #pragma unroll
            for (int j = 0; j < 4; j++)
                acc[i][j] += a[i] * bb[j];
    }

    float* Sp = g_s + (size_t)bh * LL;
    const float* Mp = mask + (size_t)b * LL;
    #pragma unroll
    for (int i = 0; i < 4; i++) {
        int r = i0 + ty * 4 + i;
        #pragma unroll
        for (int j = 0; j < 4; j++) {
            int c = j0 + tx * 4 + j;
            Sp[r * Ls + c] = acc[i][j] * 0.125f + Mp[r * Ls + c];
        }
    }
}

// ---------------------------------------------------------------------------
// Row-wise softmax in place over g_s. One 256-thread block per row of 1024.
// ---------------------------------------------------------------------------
__global__ __launch_bounds__(256) void softmax_kernel()
{
    __shared__ float sh[8];
    size_t row = blockIdx.x;
    float4* p = reinterpret_cast<float4*>(g_s) + row * 256 + threadIdx.x;
    float4 v = *p;

    float m = fmaxf(fmaxf(v.x, v.y), fmaxf(v.z, v.w));
    #pragma unroll
    for (int o = 16; o; o >>= 1) m = fmaxf(m, __shfl_xor_sync(0xffffffffu, m, o));
    if ((threadIdx.x & 31) == 0) sh[threadIdx.x >> 5] = m;
    __syncthreads();
    m = fmaxf(fmaxf(fmaxf(sh[0], sh[1]), fmaxf(sh[2], sh[3])),
              fmaxf(fmaxf(sh[4], sh[5]), fmaxf(sh[6], sh[7])));
    __syncthreads();

    v.x = __expf(v.x - m); v.y = __expf(v.y - m);
    v.z = __expf(v.z - m); v.w = __expf(v.w - m);
    float s = v.x + v.y + v.z + v.w;
    #pragma unroll
    for (int o = 16; o; o >>= 1) s += __shfl_xor_sync(0xffffffffu, s, o);
    if ((threadIdx.x & 31) == 0) sh[threadIdx.x >> 5] = s;
    __syncthreads();
    s = (sh[0] + sh[1]) + (sh[2] + sh[3]) + (sh[4] + sh[5]) + (sh[6] + sh[7]);

    float inv = 1.0f / s;
    v.x *= inv; v.y *= inv; v.z *= inv; v.w *= inv;
    *p = v;
}

// ---------------------------------------------------------------------------
// avg_weights[b, i, j] = mean over h of softmax weights
// ---------------------------------------------------------------------------
__global__ __launch_bounds__(256) void avg_kernel(float* __restrict__ out2)
{
    int idx = blockIdx.x * 256 + threadIdx.x;      // < 4*1024*1024
    int b = idx >> 20;
    int rem = idx & (LL - 1);
    const float* base = g_s + (size_t)b * Hs * LL + rem;
    float s = 0.f;
    #pragma unroll
    for (int h = 0; h < Hs; h++) s += base[(size_t)h * LL];
    out2[idx] = s * (1.0f / Hs);
}

// ---------------------------------------------------------------------------
// ctx[i, b, h*64+d] = sum_j W[bh,i,j] * V[bh,j,d]
// 64(M) x 64(N=HD) tile, BK=32.
// ---------------------------------------------------------------------------
__global__ __launch_bounds__(256) void attnv_kernel()
{
    const int bh = blockIdx.z;
    const int b = bh >> 4;
    const int h = bh & 15;
    __shared__ float Ss[32][65];
    __shared__ float Vs[32][65];
    const int tx = threadIdx.x, ty = threadIdx.y;
    const int tid = ty * 16 + tx;
    const int i0 = blockIdx.y * 64;

    const float* Sp = g_s + (size_t)bh * LL;
    float acc[4][4] = {};

    for (int j0 = 0; j0 < Ls; j0 += 32) {
        #pragma unroll
        for (int t = 0; t < 8; t++) {              // 64*32/256 = 8
            int idx = tid + t * 256;
            int m = idx >> 5, kk = idx & 31;
            Ss[kk][m] = Sp[(i0 + m) * Ls + j0 + kk];
        }
        #pragma unroll
        for (int t = 0; t < 8; t++) {
            int idx = tid + t * 256;
            int kk = idx >> 6, d = idx & 63;
            Vs[kk][d] = g_v[((j0 + kk) * Bb + b) * Es + h * 64 + d];
        }
        __syncthreads();
        #pragma unroll
        for (int kk = 0; kk < 32; kk++) {
            float a[4], bb[4];
            #pragma unroll
            for (int i = 0; i < 4; i++) a[i] = Ss[kk][ty * 4 + i];
            #pragma unroll
            for (int j = 0; j < 4; j++) bb[j] = Vs[kk][tx * 4 + j];
            #pragma unroll
            for (int i = 0; i < 4; i++)
                #pragma unroll
                for (int j = 0; j < 4; j++)
                    acc[i][j] += a[i] * bb[j];
        }
        __syncthreads();
    }

    #pragma unroll
    for (int i = 0; i < 4; i++) {
        int r = i0 + ty * 4 + i;
        #pragma unroll
        for (int j = 0; j < 4; j++) {
            int d = tx * 4 + j;
            g_ctx[(r * Bb + b) * Es + h * 64 + d] = acc[i][j];
        }
    }
}

// ---------------------------------------------------------------------------
extern "C" void kernel_launch(void* const* d_in, const int* in_sizes, int n_in,
                              void* d_out, int out_size)
{
    const float* query = (const float*)d_in[0];
    const float* key   = (const float*)d_in[1];
    const float* value = (const float*)d_in[2];
    const float* mask  = (const float*)d_in[3];
    const float* w_in  = (const float*)d_in[4];
    const float* b_in  = (const float*)d_in[5];
    const float* w_out = (const float*)d_in[6];
    const float* b_out = (const float*)d_in[7];
    float* out  = (float*)d_out;                  // attn_output [L,B,E]
    float* out2 = out + (size_t)LB * Es;          // avg_weights [B,L,L]

    float *pq, *pk, *pv, *pctx;
    cudaGetSymbolAddress((void**)&pq,   g_q);
    cudaGetSymbolAddress((void**)&pk,   g_k);
    cudaGetSymbolAddress((void**)&pv,   g_v);
    cudaGetSymbolAddress((void**)&pctx, g_ctx);

    dim3 blk(16, 16);
    dim3 gproj(Es / 64, LB / 64);                  // (16, 64)

    sgemm_nt_kernel<<<gproj, blk>>>(query, w_in,                 b_in,          pq);
    sgemm_nt_kernel<<<gproj, blk>>>(key,   w_in + Es * Es,       b_in + Es,     pk);
    sgemm_nt_kernel<<<gproj, blk>>>(value, w_in + 2 * Es * Es,   b_in + 2 * Es, pv);

    scores_kernel<<<dim3(16, 16, BH), blk>>>(mask);
    softmax_kernel<<<BH * Ls, 256>>>();
    avg_kernel<<<(Bb * LL) / 256, 256>>>(out2);
    attnv_kernel<<<dim3(1, 16, BH), blk>>>();

    sgemm_nt_kernel<<<gproj, blk>>>(pctx, w_out, b_out, out);
}

// round 4
// speedup vs baseline: 3.1988x; 3.1988x over previous
#include <cuda_runtime.h>
#include <cstdint>

#define Ls 1024
#define Bb 4
#define Es 1024
#define Hs 16
#define LB (Ls*Bb)        // 4096
#define BH (Bb*Hs)        // 64
#define LL (Ls*Ls)        // 1048576

// Scratch (device globals — allocation-free)
__device__ float g_q[LB*Es];
__device__ float g_k[LB*Es];
__device__ float g_v[LB*Es];
__device__ float g_ctx[LB*Es];
__device__ float g_s[(size_t)BH*LL];      // 256 MB scores/weights

// ---------------------------------------------------------------------------
// tf32 helpers
// ---------------------------------------------------------------------------
__device__ __forceinline__ float tf32r(float x) {
    uint32_t u;
    asm("cvt.rna.tf32.f32 %0, %1;" : "=r"(u) : "f"(x));
    return __uint_as_float(u);
}

__device__ __forceinline__ void mma_tf32(float c[4], const uint32_t a[4], const uint32_t b[2]) {
    asm volatile(
        "mma.sync.aligned.m16n8k8.row.col.f32.tf32.tf32.f32 "
        "{%0,%1,%2,%3}, {%4,%5,%6,%7}, {%8,%9}, {%0,%1,%2,%3};\n"
        : "+f"(c[0]), "+f"(c[1]), "+f"(c[2]), "+f"(c[3])
        : "r"(a[0]), "r"(a[1]), "r"(a[2]), "r"(a[3]), "r"(b[0]), "r"(b[1]));
}

// ---------------------------------------------------------------------------
// NT GEMM (tensor core): C[4096,1024] = A[4096,1024] @ W[1024,1024]^T + bias
// 128x128 tile, BK=32, 8 warps (2x4), warp tile 64x32.
// ---------------------------------------------------------------------------
__global__ __launch_bounds__(256, 2) void gemm_nt_tc(
    const float* __restrict__ A, const float* __restrict__ W,
    const float* __restrict__ bias, float* __restrict__ C)
{
    const int K = 1024, N = 1024;
    __shared__ float As[128][36];
    __shared__ float Bs[128][36];
    const int tid = threadIdx.x;
    const int lane = tid & 31, wid = tid >> 5;
    const int g = lane >> 2, t4 = lane & 3;
    const int wm = wid >> 2, wn = wid & 3;           // 2 x 4 warps
    const int row0 = blockIdx.y * 128, col0 = blockIdx.x * 128;

    float c[4][4][4] = {};

    const int lr = tid >> 3;          // 0..31
    const int lc = (tid & 7) * 4;     // 0..28

    for (int kb = 0; kb < K; kb += 32) {
        #pragma unroll
        for (int it = 0; it < 4; it++) {
            int r = lr + it * 32;
            float4 va = *(const float4*)&A[(size_t)(row0 + r) * K + kb + lc];
            As[r][lc + 0] = tf32r(va.x); As[r][lc + 1] = tf32r(va.y);
            As[r][lc + 2] = tf32r(va.z); As[r][lc + 3] = tf32r(va.w);
            float4 vb = *(const float4*)&W[(size_t)(col0 + r) * K + kb + lc];
            Bs[r][lc + 0] = tf32r(vb.x); Bs[r][lc + 1] = tf32r(vb.y);
            Bs[r][lc + 2] = tf32r(vb.z); Bs[r][lc + 3] = tf32r(vb.w);
        }
        __syncthreads();
        #pragma unroll
        for (int ks = 0; ks < 32; ks += 8) {
            uint32_t a[4][4], b[4][2];
            #pragma unroll
            for (int i = 0; i < 4; i++) {
                int m = wm * 64 + i * 16;
                a[i][0] = __float_as_uint(As[m + g][ks + t4]);
                a[i][1] = __float_as_uint(As[m + g + 8][ks + t4]);
                a[i][2] = __float_as_uint(As[m + g][ks + t4 + 4]);
                a[i][3] = __float_as_uint(As[m + g + 8][ks + t4 + 4]);
            }
            #pragma unroll
            for (int j = 0; j < 4; j++) {
                int n = wn * 32 + j * 8;
                b[j][0] = __float_as_uint(Bs[n + g][ks + t4]);
                b[j][1] = __float_as_uint(Bs[n + g][ks + t4 + 4]);
            }
            #pragma unroll
            for (int i = 0; i < 4; i++)
                #pragma unroll
                for (int j = 0; j < 4; j++)
                    mma_tf32(c[i][j], a[i], b[j]);
        }
        __syncthreads();
    }

    #pragma unroll
    for (int i = 0; i < 4; i++) {
        int r = row0 + wm * 64 + i * 16 + g;
        #pragma unroll
        for (int j = 0; j < 4; j++) {
            int cc = col0 + wn * 32 + j * 8 + 2 * t4;
            float2 bv = *(const float2*)&bias[cc];
            float2 v0 = { c[i][j][0] + bv.x, c[i][j][1] + bv.y };
            float2 v1 = { c[i][j][2] + bv.x, c[i][j][3] + bv.y };
            *(float2*)&C[(size_t)r * N + cc] = v0;
            *(float2*)&C[(size_t)(r + 8) * N + cc] = v1;
        }
    }
}

// ---------------------------------------------------------------------------
// Scores (tensor core): S[bh,i,j] = 0.125 * Q[bh,i,:]·K[bh,j,:] + mask[b,i,j]
// 128x128 tile over LxL, K=64 in two BK=32 halves.
// ---------------------------------------------------------------------------
__global__ __launch_bounds__(256, 2) void scores_tc(const float* __restrict__ mask)
{
    __shared__ float Qs[128][36];
    __shared__ float Ks[128][36];
    const int bh = blockIdx.z;
    const int b = bh >> 4, h = bh & 15;
    const int tid = threadIdx.x;
    const int lane = tid & 31, wid = tid >> 5;
    const int g = lane >> 2, t4 = lane & 3;
    const int wm = wid >> 2, wn = wid & 3;
    const int i0 = blockIdx.y * 128, j0 = blockIdx.x * 128;

    float c[4][4][4] = {};

    const int lr = tid >> 3;
    const int lc = (tid & 7) * 4;

    for (int kb = 0; kb < 64; kb += 32) {
        #pragma unroll
        for (int it = 0; it < 4; it++) {
            int r = lr + it * 32;
            float4 vq = *(const float4*)&g_q[((size_t)(i0 + r) * Bb + b) * Es + h * 64 + kb + lc];
            Qs[r][lc + 0] = tf32r(vq.x); Qs[r][lc + 1] = tf32r(vq.y);
            Qs[r][lc + 2] = tf32r(vq.z); Qs[r][lc + 3] = tf32r(vq.w);
            float4 vk = *(const float4*)&g_k[((size_t)(j0 + r) * Bb + b) * Es + h * 64 + kb + lc];
            Ks[r][lc + 0] = tf32r(vk.x); Ks[r][lc + 1] = tf32r(vk.y);
            Ks[r][lc + 2] = tf32r(vk.z); Ks[r][lc + 3] = tf32r(vk.w);
        }
        __syncthreads();
        #pragma unroll
        for (int ks = 0; ks < 32; ks += 8) {
            uint32_t a[4][4], b2[4][2];
            #pragma unroll
            for (int i = 0; i < 4; i++) {
                int m = wm * 64 + i * 16;
                a[i][0] = __float_as_uint(Qs[m + g][ks + t4]);
                a[i][1] = __float_as_uint(Qs[m + g + 8][ks + t4]);
                a[i][2] = __float_as_uint(Qs[m + g][ks + t4 + 4]);
                a[i][3] = __float_as_uint(Qs[m + g + 8][ks + t4 + 4]);
            }
            #pragma unroll
            for (int j = 0; j < 4; j++) {
                int n = wn * 32 + j * 8;
                b2[j][0] = __float_as_uint(Ks[n + g][ks + t4]);
                b2[j][1] = __float_as_uint(Ks[n + g][ks + t4 + 4]);
            }
            #pragma unroll
            for (int i = 0; i < 4; i++)
                #pragma unroll
                for (int j = 0; j < 4; j++)
                    mma_tf32(c[i][j], a[i], b2[j]);
        }
        __syncthreads();
    }

    float* Sp = g_s + (size_t)bh * LL;
    const float* Mp = mask + (size_t)b * LL;
    #pragma unroll
    for (int i = 0; i < 4; i++) {
        int r = i0 + wm * 64 + i * 16 + g;
        #pragma unroll
        for (int j = 0; j < 4; j++) {
            int cc = j0 + wn * 32 + j * 8 + 2 * t4;
            float2 m0 = *(const float2*)&Mp[(size_t)r * Ls + cc];
            float2 m1 = *(const float2*)&Mp[(size_t)(r + 8) * Ls + cc];
            float2 v0 = { c[i][j][0] * 0.125f + m0.x, c[i][j][1] * 0.125f + m0.y };
            float2 v1 = { c[i][j][2] * 0.125f + m1.x, c[i][j][3] * 0.125f + m1.y };
            *(float2*)&Sp[(size_t)r * Ls + cc] = v0;
            *(float2*)&Sp[(size_t)(r + 8) * Ls + cc] = v1;
        }
    }
}

// ---------------------------------------------------------------------------
// Row-wise softmax in place over g_s. One 256-thread block per row of 1024.
// ---------------------------------------------------------------------------
__global__ __launch_bounds__(256) void softmax_kernel()
{
    __shared__ float sh[8];
    size_t row = blockIdx.x;
    float4* p = reinterpret_cast<float4*>(g_s) + row * 256 + threadIdx.x;
    float4 v = *p;

    float m = fmaxf(fmaxf(v.x, v.y), fmaxf(v.z, v.w));
    #pragma unroll
    for (int o = 16; o; o >>= 1) m = fmaxf(m, __shfl_xor_sync(0xffffffffu, m, o));
    if ((threadIdx.x & 31) == 0) sh[threadIdx.x >> 5] = m;
    __syncthreads();
    m = fmaxf(fmaxf(fmaxf(sh[0], sh[1]), fmaxf(sh[2], sh[3])),
              fmaxf(fmaxf(sh[4], sh[5]), fmaxf(sh[6], sh[7])));
    __syncthreads();

    v.x = __expf(v.x - m); v.y = __expf(v.y - m);
    v.z = __expf(v.z - m); v.w = __expf(v.w - m);
    float s = v.x + v.y + v.z + v.w;
    #pragma unroll
    for (int o = 16; o; o >>= 1) s += __shfl_xor_sync(0xffffffffu, s, o);
    if ((threadIdx.x & 31) == 0) sh[threadIdx.x >> 5] = s;
    __syncthreads();
    s = (sh[0] + sh[1]) + (sh[2] + sh[3]) + (sh[4] + sh[5]) + (sh[6] + sh[7]);

    float inv = 1.0f / s;
    v.x *= inv; v.y *= inv; v.z *= inv; v.w *= inv;
    *p = v;
}

// ---------------------------------------------------------------------------
// avg_weights[b, i, j] = mean over h of softmax weights
// ---------------------------------------------------------------------------
__global__ __launch_bounds__(256) void avg_kernel(float* __restrict__ out2)
{
    int idx = blockIdx.x * 256 + threadIdx.x;      // < 4*1024*1024
    int b = idx >> 20;
    int rem = idx & (LL - 1);
    const float* base = g_s + (size_t)b * Hs * LL + rem;
    float s = 0.f;
    #pragma unroll
    for (int h = 0; h < Hs; h++) s += base[(size_t)h * LL];
    out2[idx] = s * (1.0f / Hs);
}

// ---------------------------------------------------------------------------
// AttnV (tensor core): ctx[i,b,h*64+d] = sum_j W[bh,i,j] * V[bh,j,d]
// 128(M) x 64(N=HD) tile, BK=32, 8 warps (4x2), warp tile 32x32.
// ---------------------------------------------------------------------------
__global__ __launch_bounds__(256, 2) void attnv_tc()
{
    __shared__ float Ss[128][36];
    __shared__ float Vs[32][72];
    const int bh = blockIdx.y;
    const int b = bh >> 4, h = bh & 15;
    const int tid = threadIdx.x;
    const int lane = tid & 31, wid = tid >> 5;
    const int g = lane >> 2, t4 = lane & 3;
    const int wm = wid >> 1, wn = wid & 1;           // 4 x 2 warps
    const int i0 = blockIdx.x * 128;

    const float* Sp = g_s + (size_t)bh * LL;
    float c[2][4][4] = {};

    const int lr = tid >> 3;
    const int lc = (tid & 7) * 4;

    for (int kb = 0; kb < Ls; kb += 32) {
        #pragma unroll
        for (int it = 0; it < 4; it++) {
            int r = lr + it * 32;
            float4 vs = *(const float4*)&Sp[(size_t)(i0 + r) * Ls + kb + lc];
            Ss[r][lc + 0] = tf32r(vs.x); Ss[r][lc + 1] = tf32r(vs.y);
            Ss[r][lc + 2] = tf32r(vs.z); Ss[r][lc + 3] = tf32r(vs.w);
        }
        #pragma unroll
        for (int it = 0; it < 2; it++) {
            int idx = tid + it * 256;
            int j = idx >> 4, d4 = (idx & 15) * 4;
            float4 vv = *(const float4*)&g_v[((size_t)(kb + j) * Bb + b) * Es + h * 64 + d4];
            Vs[j][d4 + 0] = tf32r(vv.x); Vs[j][d4 + 1] = tf32r(vv.y);
            Vs[j][d4 + 2] = tf32r(vv.z); Vs[j][d4 + 3] = tf32r(vv.w);
        }
        __syncthreads();
        #pragma unroll
        for (int ks = 0; ks < 32; ks += 8) {
            uint32_t a[2][4], b2[4][2];
            #pragma unroll
            for (int i = 0; i < 2; i++) {
                int m = wm * 32 + i * 16;
                a[i][0] = __float_as_uint(Ss[m + g][ks + t4]);
                a[i][1] = __float_as_uint(Ss[m + g + 8][ks + t4]);
                a[i][2] = __float_as_uint(Ss[m + g][ks + t4 + 4]);
                a[i][3] = __float_as_uint(Ss[m + g + 8][ks + t4 + 4]);
            }
            #pragma unroll
            for (int j = 0; j < 4; j++) {
                int n = wn * 32 + j * 8;
                b2[j][0] = __float_as_uint(Vs[ks + t4][n + g]);
                b2[j][1] = __float_as_uint(Vs[ks + t4 + 4][n + g]);
            }
            #pragma unroll
            for (int i = 0; i < 2; i++)
                #pragma unroll
                for (int j = 0; j < 4; j++)
                    mma_tf32(c[i][j], a[i], b2[j]);
        }
        __syncthreads();
    }

    #pragma unroll
    for (int i = 0; i < 2; i++) {
        int r = i0 + wm * 32 + i * 16 + g;
        #pragma unroll
        for (int j = 0; j < 4; j++) {
            int d = wn * 32 + j * 8 + 2 * t4;
            float2 v0 = { c[i][j][0], c[i][j][1] };
            float2 v1 = { c[i][j][2], c[i][j][3] };
            *(float2*)&g_ctx[((size_t)r * Bb + b) * Es + h * 64 + d] = v0;
            *(float2*)&g_ctx[((size_t)(r + 8) * Bb + b) * Es + h * 64 + d] = v1;
        }
    }
}

// ---------------------------------------------------------------------------
extern "C" void kernel_launch(void* const* d_in, const int* in_sizes, int n_in,
                              void* d_out, int out_size)
{
    const float* query = (const float*)d_in[0];
    const float* key   = (const float*)d_in[1];
    const float* value = (const float*)d_in[2];
    const float* mask  = (const float*)d_in[3];
    const float* w_in  = (const float*)d_in[4];
    const float* b_in  = (const float*)d_in[5];
    const float* w_out = (const float*)d_in[6];
    const float* b_out = (const float*)d_in[7];
    float* out  = (float*)d_out;                  // attn_output [L,B,E]
    float* out2 = out + (size_t)LB * Es;          // avg_weights [B,L,L]

    float *pq, *pk, *pv, *pctx;
    cudaGetSymbolAddress((void**)&pq,   g_q);
    cudaGetSymbolAddress((void**)&pk,   g_k);
    cudaGetSymbolAddress((void**)&pv,   g_v);
    cudaGetSymbolAddress((void**)&pctx, g_ctx);

    dim3 gproj(Es / 128, LB / 128);                // (8, 32)

    gemm_nt_tc<<<gproj, 256>>>(query, w_in,               b_in,          pq);
    gemm_nt_tc<<<gproj, 256>>>(key,   w_in + Es * Es,     b_in + Es,     pk);
    gemm_nt_tc<<<gproj, 256>>>(value, w_in + 2 * Es * Es, b_in + 2 * Es, pv);

    scores_tc<<<dim3(8, 8, BH), 256>>>(mask);
    softmax_kernel<<<BH * Ls, 256>>>();
    avg_kernel<<<(Bb * LL) / 256, 256>>>(out2);
    attnv_tc<<<dim3(8, BH), 256>>>();

    gemm_nt_tc<<<gproj, 256>>>(pctx, w_out, b_out, out);
}

// round 6
// speedup vs baseline: 3.5989x; 1.1251x over previous
#include <cuda_runtime.h>
#include <cstdint>
#include <math_constants.h>

#define Ls 1024
#define Bb 4
#define Es 1024
#define Hs 16
#define LB (Ls*Bb)        // 4096
#define BH (Bb*Hs)        // 64
#define LL (Ls*Ls)        // 1048576

// Scratch (device globals — allocation-free)
__device__ float g_q[LB*Es];
__device__ float g_k[LB*Es];
__device__ float g_v[LB*Es];
__device__ float g_ctx[LB*Es];
__device__ float g_s[(size_t)BH*LL];       // 256 MB raw masked scores
__device__ float2 g_stats[BH*Ls];          // per-row (max, 1/Z)

// ---------------------------------------------------------------------------
// tf32 helpers
// ---------------------------------------------------------------------------
__device__ __forceinline__ float tf32r(float x) {
    uint32_t u;
    asm("cvt.rna.tf32.f32 %0, %1;" : "=r"(u) : "f"(x));
    return __uint_as_float(u);
}

__device__ __forceinline__ void mma_tf32(float c[4], const uint32_t a[4], const uint32_t b[2]) {
    asm volatile(
        "mma.sync.aligned.m16n8k8.row.col.f32.tf32.tf32.f32 "
        "{%0,%1,%2,%3}, {%4,%5,%6,%7}, {%8,%9}, {%0,%1,%2,%3};\n"
        : "+f"(c[0]), "+f"(c[1]), "+f"(c[2]), "+f"(c[3])
        : "r"(a[0]), "r"(a[1]), "r"(a[2]), "r"(a[3]), "r"(b[0]), "r"(b[1]));
}

// ---------------------------------------------------------------------------
// NT GEMM (tensor core): C[4096,1024] = A[4096,1024] @ W[1024,1024]^T + bias
// 128x128 tile, BK=32, 8 warps (2x4), warp tile 64x32.
// ---------------------------------------------------------------------------
__global__ __launch_bounds__(256, 2) void gemm_nt_tc(
    const float* __restrict__ A, const float* __restrict__ W,
    const float* __restrict__ bias, float* __restrict__ C)
{
    const int K = 1024, N = 1024;
    __shared__ float As[128][36];
    __shared__ float Bs[128][36];
    const int tid = threadIdx.x;
    const int lane = tid & 31, wid = tid >> 5;
    const int g = lane >> 2, t4 = lane & 3;
    const int wm = wid >> 2, wn = wid & 3;           // 2 x 4 warps
    const int row0 = blockIdx.y * 128, col0 = blockIdx.x * 128;

    float c[4][4][4] = {};

    const int lr = tid >> 3;          // 0..31
    const int lc = (tid & 7) * 4;     // 0..28

    for (int kb = 0; kb < K; kb += 32) {
        #pragma unroll
        for (int it = 0; it < 4; it++) {
            int r = lr + it * 32;
            float4 va = *(const float4*)&A[(size_t)(row0 + r) * K + kb + lc];
            As[r][lc + 0] = tf32r(va.x); As[r][lc + 1] = tf32r(va.y);
            As[r][lc + 2] = tf32r(va.z); As[r][lc + 3] = tf32r(va.w);
            float4 vb = *(const float4*)&W[(size_t)(col0 + r) * K + kb + lc];
            Bs[r][lc + 0] = tf32r(vb.x); Bs[r][lc + 1] = tf32r(vb.y);
            Bs[r][lc + 2] = tf32r(vb.z); Bs[r][lc + 3] = tf32r(vb.w);
        }
        __syncthreads();
        #pragma unroll
        for (int ks = 0; ks < 32; ks += 8) {
            uint32_t a[4][4], b[4][2];
            #pragma unroll
            for (int i = 0; i < 4; i++) {
                int m = wm * 64 + i * 16;
                a[i][0] = __float_as_uint(As[m + g][ks + t4]);
                a[i][1] = __float_as_uint(As[m + g + 8][ks + t4]);
                a[i][2] = __float_as_uint(As[m + g][ks + t4 + 4]);
                a[i][3] = __float_as_uint(As[m + g + 8][ks + t4 + 4]);
            }
            #pragma unroll
            for (int j = 0; j < 4; j++) {
                int n = wn * 32 + j * 8;
                b[j][0] = __float_as_uint(Bs[n + g][ks + t4]);
                b[j][1] = __float_as_uint(Bs[n + g][ks + t4 + 4]);
            }
            #pragma unroll
            for (int i = 0; i < 4; i++)
                #pragma unroll
                for (int j = 0; j < 4; j++)
                    mma_tf32(c[i][j], a[i], b[j]);
        }
        __syncthreads();
    }

    #pragma unroll
    for (int i = 0; i < 4; i++) {
        int r = row0 + wm * 64 + i * 16 + g;
        #pragma unroll
        for (int j = 0; j < 4; j++) {
            int cc = col0 + wn * 32 + j * 8 + 2 * t4;
            float2 bv = *(const float2*)&bias[cc];
            float2 v0 = { c[i][j][0] + bv.x, c[i][j][1] + bv.y };
            float2 v1 = { c[i][j][2] + bv.x, c[i][j][3] + bv.y };
            *(float2*)&C[(size_t)r * N + cc] = v0;
            *(float2*)&C[(size_t)(r + 8) * N + cc] = v1;
        }
    }
}

// ---------------------------------------------------------------------------
// scores2: one block per (bh, 128-row i-tile). Loops over all 8 j-tiles of 128.
// Writes raw masked scores to g_s AND accumulates per-row online softmax stats
// (running max m, running sum Z) in SMEM; writes (m, 1/Z) to g_stats.
// Dynamic SMEM layout (floats):
//   Qs[128][68] @0, Ks[128][68] @8704, pm[4][128] @17408, pz[4][128] @17920,
//   rm[128] @18432, rz[128] @18560   (total 18688 floats = 74752 B)
// ---------------------------------------------------------------------------
#define SC_SMEM_FLOATS 18688
__global__ __launch_bounds__(256, 2) void scores2(const float* __restrict__ mask)
{
    extern __shared__ float sm[];
    float* Qs = sm;
    float* Ks = sm + 8704;
    float* pm = sm + 17408;
    float* pz = sm + 17920;
    float* rm = sm + 18432;
    float* rz = sm + 18560;

    const int bh = blockIdx.y;
    const int b = bh >> 4, h = bh & 15;
    const int i0 = blockIdx.x * 128;
    const int tid = threadIdx.x;
    const int lane = tid & 31, wid = tid >> 5;
    const int g = lane >> 2, t4 = lane & 3;
    const int wm = wid >> 2, wn = wid & 3;          // 2 x 4 warps, warp tile 64x32

    if (tid < 128) { rm[tid] = -CUDART_INF_F; rz[tid] = 0.f; }

    // Load Q tile [128 x 64] once (tf32-rounded), stride 68
    #pragma unroll
    for (int it = 0; it < 8; it++) {
        int idx = tid + it * 256;                   // 2048 float4 slots
        int r = idx >> 4, cc = (idx & 15) * 4;
        float4 v = *(const float4*)&g_q[((size_t)(i0 + r) * Bb + b) * Es + h * 64 + cc];
        Qs[r * 68 + cc + 0] = tf32r(v.x); Qs[r * 68 + cc + 1] = tf32r(v.y);
        Qs[r * 68 + cc + 2] = tf32r(v.z); Qs[r * 68 + cc + 3] = tf32r(v.w);
    }
    __syncthreads();

    float* Sp = g_s + (size_t)bh * LL;
    const float* Mp = mask + (size_t)b * LL;

    for (int j0 = 0; j0 < Ls; j0 += 128) {
        // Load K tile [128 x 64]
        #pragma unroll
        for (int it = 0; it < 8; it++) {
            int idx = tid + it * 256;
            int r = idx >> 4, cc = (idx & 15) * 4;
            float4 v = *(const float4*)&g_k[((size_t)(j0 + r) * Bb + b) * Es + h * 64 + cc];
            Ks[r * 68 + cc + 0] = tf32r(v.x); Ks[r * 68 + cc + 1] = tf32r(v.y);
            Ks[r * 68 + cc + 2] = tf32r(v.z); Ks[r * 68 + cc + 3] = tf32r(v.w);
        }
        __syncthreads();

        float c[4][4][4] = {};
        #pragma unroll
        for (int ks = 0; ks < 64; ks += 8) {
            uint32_t a[4][4], b2[4][2];
            #pragma unroll
            for (int i = 0; i < 4; i++) {
                int m = wm * 64 + i * 16;
                a[i][0] = __float_as_uint(Qs[(m + g) * 68 + ks + t4]);
                a[i][1] = __float_as_uint(Qs[(m + g + 8) * 68 + ks + t4]);
                a[i][2] = __float_as_uint(Qs[(m + g) * 68 + ks + t4 + 4]);
                a[i][3] = __float_as_uint(Qs[(m + g + 8) * 68 + ks + t4 + 4]);
            }
            #pragma unroll
            for (int j = 0; j < 4; j++) {
                int n = wn * 32 + j * 8;
                b2[j][0] = __float_as_uint(Ks[(n + g) * 68 + ks + t4]);
                b2[j][1] = __float_as_uint(Ks[(n + g) * 68 + ks + t4 + 4]);
            }
            #pragma unroll
            for (int i = 0; i < 4; i++)
                #pragma unroll
                for (int j = 0; j < 4; j++)
                    mma_tf32(c[i][j], a[i], b2[j]);
        }

        // Epilogue: mask+scale into c, store raw, then per-row stats
        #pragma unroll
        for (int i = 0; i < 4; i++) {
            int r = i0 + wm * 64 + i * 16 + g;
            #pragma unroll
            for (int j = 0; j < 4; j++) {
                int cc = j0 + wn * 32 + j * 8 + 2 * t4;
                float2 m0 = *(const float2*)&Mp[(size_t)r * Ls + cc];
                float2 m1 = *(const float2*)&Mp[(size_t)(r + 8) * Ls + cc];
                c[i][j][0] = c[i][j][0] * 0.125f + m0.x;
                c[i][j][1] = c[i][j][1] * 0.125f + m0.y;
                c[i][j][2] = c[i][j][2] * 0.125f + m1.x;
                c[i][j][3] = c[i][j][3] * 0.125f + m1.y;
                float2 v0 = { c[i][j][0], c[i][j][1] };
                float2 v1 = { c[i][j][2], c[i][j][3] };
                *(float2*)&Sp[(size_t)r * Ls + cc] = v0;
                *(float2*)&Sp[(size_t)(r + 8) * Ls + cc] = v1;
            }
        }

        // Per-thread tile-local stats: 8 rows (i x {g, g+8}), 8 vals each
        #pragma unroll
        for (int i = 0; i < 4; i++) {
            #pragma unroll
            for (int sub = 0; sub < 2; sub++) {
                float tm = c[i][0][2 * sub];
                #pragma unroll
                for (int j = 0; j < 4; j++) {
                    tm = fmaxf(tm, c[i][j][2 * sub + 0]);
                    tm = fmaxf(tm, c[i][j][2 * sub + 1]);
                }
                float ts = 0.f;
                #pragma unroll
                for (int j = 0; j < 4; j++) {
                    ts += __expf(c[i][j][2 * sub + 0] - tm);
                    ts += __expf(c[i][j][2 * sub + 1] - tm);
                }
                // merge across t4 lanes (same row held by 4 lanes)
                #pragma unroll
                for (int o = 1; o < 4; o <<= 1) {
                    float om = __shfl_xor_sync(0xffffffffu, tm, o);
                    float os = __shfl_xor_sync(0xffffffffu, ts, o);
                    float nm = fmaxf(tm, om);
                    ts = ts * __expf(tm - nm) + os * __expf(om - nm);
                    tm = nm;
                }
                if (t4 == 0) {
                    int rr = wm * 64 + i * 16 + g + 8 * sub;
                    pm[wn * 128 + rr] = tm;
                    pz[wn * 128 + rr] = ts;
                }
            }
        }
        __syncthreads();

        if (tid < 128) {
            float nm = rm[tid], nz = rz[tid];
            #pragma unroll
            for (int w = 0; w < 4; w++) {
                float tm = pm[w * 128 + tid], ts = pz[w * 128 + tid];
                float mx = fmaxf(nm, tm);
                nz = nz * __expf(nm - mx) + ts * __expf(tm - mx);
                nm = mx;
            }
            rm[tid] = nm; rz[tid] = nz;
        }
        __syncthreads();
    }

    if (tid < 128) {
        float2 st = { rm[tid], 1.0f / rz[tid] };
        g_stats[bh * Ls + i0 + tid] = st;
    }
}

// ---------------------------------------------------------------------------
// avg_weights[b,i,j] = (1/H) * sum_h exp(s[bh,i,j]-m)*invZ    (vectorized x4)
// ---------------------------------------------------------------------------
__global__ __launch_bounds__(256) void avg_kernel(float* __restrict__ out2)
{
    int idx = blockIdx.x * 256 + threadIdx.x;      // < 1M float4 units
    int b = idx >> 18;
    int rem = idx & 262143;
    int i = rem >> 8;
    int j = (rem & 255) * 4;
    float4 acc = { 0.f, 0.f, 0.f, 0.f };
    #pragma unroll
    for (int h = 0; h < Hs; h++) {
        int bh = b * Hs + h;
        float4 v = *(const float4*)&g_s[(size_t)bh * LL + (size_t)i * Ls + j];
        float2 st = g_stats[bh * Ls + i];
        acc.x += __expf(v.x - st.x) * st.y;
        acc.y += __expf(v.y - st.x) * st.y;
        acc.z += __expf(v.z - st.x) * st.y;
        acc.w += __expf(v.w - st.x) * st.y;
    }
    const float sc = 1.0f / Hs;
    acc.x *= sc; acc.y *= sc; acc.z *= sc; acc.w *= sc;
    *(float4*)&out2[(size_t)idx * 4] = acc;
}

// ---------------------------------------------------------------------------
// AttnV (tensor core): ctx = softmax(S)·V. Reads raw s, stages w=exp(s-m),
// scales output rows by invZ. 128(M) x 64(N=HD) tile, BK=32, 8 warps (4x2).
// ---------------------------------------------------------------------------
__global__ __launch_bounds__(256, 2) void attnv_tc()
{
    __shared__ float Ss[128][36];
    __shared__ float Vs[32][72];
    const int bh = blockIdx.y;
    const int b = bh >> 4, h = bh & 15;
    const int tid = threadIdx.x;
    const int lane = tid & 31, wid = tid >> 5;
    const int g = lane >> 2, t4 = lane & 3;
    const int wm = wid >> 1, wn = wid & 1;           // 4 x 2 warps
    const int i0 = blockIdx.x * 128;

    const float* Sp = g_s + (size_t)bh * LL;
    float c[2][4][4] = {};

    const int lr = tid >> 3;
    const int lc = (tid & 7) * 4;

    // per-thread row stats for the 4 staging rows
    float mrow[4];
    #pragma unroll
    for (int it = 0; it < 4; it++)
        mrow[it] = g_stats[bh * Ls + i0 + lr + it * 32].x;

    for (int kb = 0; kb < Ls; kb += 32) {
        #pragma unroll
        for (int it = 0; it < 4; it++) {
            int r = lr + it * 32;
            float4 vs = *(const float4*)&Sp[(size_t)(i0 + r) * Ls + kb + lc];
            Ss[r][lc + 0] = tf32r(__expf(vs.x - mrow[it]));
            Ss[r][lc + 1] = tf32r(__expf(vs.y - mrow[it]));
            Ss[r][lc + 2] = tf32r(__expf(vs.z - mrow[it]));
            Ss[r][lc + 3] = tf32r(__expf(vs.w - mrow[it]));
        }
        #pragma unroll
        for (int it = 0; it < 2; it++) {
            int idx = tid + it * 256;
            int j = idx >> 4, d4 = (idx & 15) * 4;
            float4 vv = *(const float4*)&g_v[((size_t)(kb + j) * Bb + b) * Es + h * 64 + d4];
            Vs[j][d4 + 0] = tf32r(vv.x); Vs[j][d4 + 1] = tf32r(vv.y);
            Vs[j][d4 + 2] = tf32r(vv.z); Vs[j][d4 + 3] = tf32r(vv.w);
        }
        __syncthreads();
        #pragma unroll
        for (int ks = 0; ks < 32; ks += 8) {
            uint32_t a[2][4], b2[4][2];
            #pragma unroll
            for (int i = 0; i < 2; i++) {
                int m = wm * 32 + i * 16;
                a[i][0] = __float_as_uint(Ss[m + g][ks + t4]);
                a[i][1] = __float_as_uint(Ss[m + g + 8][ks + t4]);
                a[i][2] = __float_as_uint(Ss[m + g][ks + t4 + 4]);
                a[i][3] = __float_as_uint(Ss[m + g + 8][ks + t4 + 4]);
            }
            #pragma unroll
            for (int j = 0; j < 4; j++) {
                int n = wn * 32 + j * 8;
                b2[j][0] = __float_as_uint(Vs[ks + t4][n + g]);
                b2[j][1] = __float_as_uint(Vs[ks + t4 + 4][n + g]);
            }
            #pragma unroll
            for (int i = 0; i < 2; i++)
                #pragma unroll
                for (int j = 0; j < 4; j++)
                    mma_tf32(c[i][j], a[i], b2[j]);
        }
        __syncthreads();
    }

    #pragma unroll
    for (int i = 0; i < 2; i++) {
        int r = i0 + wm * 32 + i * 16 + g;
        float iz0 = g_stats[bh * Ls + r].y;
        float iz1 = g_stats[bh * Ls + r + 8].y;
        #pragma unroll
        for (int j = 0; j < 4; j++) {
            int d = wn * 32 + j * 8 + 2 * t4;
            float2 v0 = { c[i][j][0] * iz0, c[i][j][1] * iz0 };
            float2 v1 = { c[i][j][2] * iz1, c[i][j][3] * iz1 };
            *(float2*)&g_ctx[((size_t)r * Bb + b) * Es + h * 64 + d] = v0;
            *(float2*)&g_ctx[((size_t)(r + 8) * Bb + b) * Es + h * 64 + d] = v1;
        }
    }
}

// ---------------------------------------------------------------------------
extern "C" void kernel_launch(void* const* d_in, const int* in_sizes, int n_in,
                              void* d_out, int out_size)
{
    const float* query = (const float*)d_in[0];
    const float* key   = (const float*)d_in[1];
    const float* value = (const float*)d_in[2];
    const float* mask  = (const float*)d_in[3];
    const float* w_in  = (const float*)d_in[4];
    const float* b_in  = (const float*)d_in[5];
    const float* w_out = (const float*)d_in[6];
    const float* b_out = (const float*)d_in[7];
    float* out  = (float*)d_out;                  // attn_output [L,B,E]
    float* out2 = out + (size_t)LB * Es;          // avg_weights [B,L,L]

    float *pq, *pk, *pv, *pctx;
    cudaGetSymbolAddress((void**)&pq,   g_q);
    cudaGetSymbolAddress((void**)&pk,   g_k);
    cudaGetSymbolAddress((void**)&pv,   g_v);
    cudaGetSymbolAddress((void**)&pctx, g_ctx);

    const int SC_SMEM = SC_SMEM_FLOATS * 4;   // 74752 bytes dynamic smem for scores2
    cudaFuncSetAttribute(scores2, cudaFuncAttributeMaxDynamicSharedMemorySize, SC_SMEM);

    dim3 gproj(Es / 128, LB / 128);                // (8, 32)

    gemm_nt_tc<<<gproj, 256>>>(query, w_in,               b_in,          pq);
    gemm_nt_tc<<<gproj, 256>>>(key,   w_in + Es * Es,     b_in + Es,     pk);
    gemm_nt_tc<<<gproj, 256>>>(value, w_in + 2 * Es * Es, b_in + 2 * Es, pv);

    scores2<<<dim3(8, BH), 256, SC_SMEM>>>(mask);
    avg_kernel<<<(Bb * LL / 4) / 256, 256>>>(out2);
    attnv_tc<<<dim3(8, BH), 256>>>();

    gemm_nt_tc<<<gproj, 256>>>(pctx, w_out, b_out, out);
}